// round 14
// baseline (speedup 1.0000x reference)
#include <cuda_runtime.h>
#include <cstdint>

// ---------------- problem constants ----------------
#define NB    64
#define CIN   512
#define HDIM  28
#define WDIM  28
#define HW    784
#define PTOT  (NB*HW)       // 50176
#define WIDTH 128
#define COUT  512

// main (ldmatrix) tiling
#define G1T   784           // 64-pixel tiles
#define G2T   784
#define G3T   1568          // 128-pixel x 128-chan tiles
#define G12GRID 444         // 148 x 3
#define G3GRID  296
// fallback tiling (proven R10 kernels)
#define FB_NT1 392
#define FB_NT2 392
#define FB_NT3 1568
#define FBGRID 296

// quantization constants
#define M0_RS 1073741824LL
#define SH_RS 4
#define M0_C1 1288490189LL
#define SH_C1 12
#define M0_C2 1288490189LL
#define SH_C2 10
#define M0_C3 1288490189LL
#define SH_C3 10
#define M0_B  1073741824LL
#define SH_B  1

// ---------------- scratch ----------------
__device__ int8_t g_A1[(size_t)PTOT * CIN];
__device__ int8_t g_O1[(size_t)PTOT * WIDTH];
__device__ int8_t g_O2[(size_t)PTOT * WIDTH];
__device__ int8_t g_RX8[(size_t)PTOT * COUT];
__device__ int8_t g_W1[WIDTH * CIN];
__device__ int8_t g_W2[9 * WIDTH * WIDTH];
__device__ int8_t g_W3[COUT * WIDTH];
__device__ int    g_B1[WIDTH];
__device__ int    g_B2[WIDTH];
__device__ int    g_B3[COUT];
__device__ int8_t g_LUTA[256];
__device__ int8_t g_LUTR[256];
__device__ unsigned g_tick[8];
__device__ int    g_flag[3];

// ---------------- helpers ----------------
__device__ __forceinline__ unsigned smem_u32(const void* p) {
    return (unsigned)__cvta_generic_to_shared(p);
}
__device__ __forceinline__ void cp16(unsigned dst, const void* src) {
    asm volatile("cp.async.ca.shared.global [%0], [%1], 16;\n" :: "r"(dst), "l"(src));
}
__device__ __forceinline__ void cp16p(unsigned dst, const void* src, int src_sz) {
    asm volatile("cp.async.ca.shared.global [%0], [%1], 16, %2;\n"
                 :: "r"(dst), "l"(src), "r"(src_sz));
}
__device__ __forceinline__ void cp_commit() { asm volatile("cp.async.commit_group;\n"); }
template <int N>
__device__ __forceinline__ void cp_wait() { asm volatile("cp.async.wait_group %0;\n" :: "n"(N)); }

__device__ __forceinline__ void ldsm_x4(int* r, unsigned addr) {
    asm volatile("ldmatrix.sync.aligned.m8n8.x4.shared.b16 {%0,%1,%2,%3}, [%4];"
                 : "=r"(r[0]), "=r"(r[1]), "=r"(r[2]), "=r"(r[3]) : "r"(addr));
}

__device__ __forceinline__ int decode_in(unsigned u) {
    float f = __uint_as_float(u);
    float af = fabsf(f);
    if (af >= 1e-30f && af <= 1e7f) return __float2int_rn(f);
    return (int)u;
}
__device__ __forceinline__ long long mulM(long long x, long long m0) {
    long long prod = x * m0;
    long long nudge = (prod >= 0) ? (1LL << 30) : (1LL - (1LL << 30));
    return (prod + nudge) >> 31;
}
__device__ __forceinline__ long long rsh(long long x, int s) {
    long long mask = (1LL << s) - 1;
    long long rem = x & mask;
    long long thr = (mask >> 1) + (long long)(x < 0);
    return (x >> s) + (long long)(rem > thr);
}
__device__ __forceinline__ int clampi(int v, int lo, int hi) {
    return v < lo ? lo : (v > hi ? hi : v);
}
__device__ __forceinline__ int8_t epi1(int acc, int co) {
    long long q = rsh(mulM((long long)acc + g_B1[co], M0_C1), SH_C1) + 128;
    return (int8_t)(clampi((int)q, 0, 255) - 128);
}
__device__ __forceinline__ int8_t epi2(int acc, int co) {
    long long q = rsh(mulM((long long)acc + g_B2[co], M0_C2), SH_C2) + 128;
    return (int8_t)(clampi((int)q, 0, 255) - 128);
}
__device__ __forceinline__ int epi3_add(int acc, int co, int xval) {
    long long q = rsh(mulM((long long)acc + g_B3[co], M0_C3), SH_C3) + 128;
    int v3 = clampi((int)q, 0, 255);
    long long x1 = rsh(mulM((long long)(xval - 128), M0_B), SH_B);
    long long x2 = rsh(mulM((long long)(v3 - 128), M0_B), SH_B);
    return clampi((int)(x1 + x2 + 128), 0, 255);
}

__device__ __forceinline__ void mma_s8(int* c, const int* a, const int* b) {
    asm volatile(
        "mma.sync.aligned.m16n8k32.row.col.s32.s8.s8.s32 "
        "{%0,%1,%2,%3},{%4,%5,%6,%7},{%8,%9},{%0,%1,%2,%3};\n"
        : "+r"(c[0]), "+r"(c[1]), "+r"(c[2]), "+r"(c[3])
        : "r"(a[0]), "r"(a[1]), "r"(a[2]), "r"(a[3]), "r"(b[0]), "r"(b[1]));
}

// ---------------- weight prep ----------------
__global__ __launch_bounds__(256) void prep_weights(
        const unsigned* __restrict__ w1, const unsigned* __restrict__ b1,
        const unsigned* __restrict__ w2, const unsigned* __restrict__ b2,
        const unsigned* __restrict__ w3, const unsigned* __restrict__ b3) {
    int t = blockIdx.x * blockDim.x + threadIdx.x;
    if (t < 8) g_tick[t] = 0u;
    if (t < 3) g_flag[t] = 0;
    if (t < 256) {
        long long d = (long long)t - 128;
        long long q = rsh(mulM(d, M0_RS), SH_RS) + 8;
        g_LUTA[t] = (int8_t)(clampi((int)q, 0, 15) - 8);
        g_LUTR[t] = (int8_t)rsh(mulM(d, M0_B), SH_B);
    }
    if (t < WIDTH * CIN)  g_W1[t] = (int8_t)decode_in(w1[t]);
    if (t < COUT * WIDTH) g_W3[t] = (int8_t)decode_in(w3[t]);
    if (t < WIDTH * WIDTH * 9) {
        int co = t / (WIDTH * 9);
        int r  = t % (WIDTH * 9);
        int ci = r / 9;
        int k  = r % 9;
        g_W2[(size_t)k * WIDTH * WIDTH + (size_t)co * WIDTH + ci] =
            (int8_t)decode_in(w2[t]);
    }
    if (t < WIDTH) { g_B1[t] = decode_in(b1[t]); g_B2[t] = decode_in(b2[t]); }
    if (t < COUT)  { g_B3[t] = decode_in(b3[t]); }
}

// ---------------- rescale + transpose + residual ----------------
__global__ __launch_bounds__(256) void rescale_kernel(const unsigned* __restrict__ x) {
    __shared__ int8_t tile[32][33];
    __shared__ int8_t sLA[256], sLR[256];
    int n  = blockIdx.z;
    int c0 = blockIdx.y * 32;
    int p0 = blockIdx.x * 32;
    int tx = threadIdx.x, ty = threadIdx.y;
    int tid = ty * 32 + tx;
    sLA[tid] = g_LUTA[tid];
    sLR[tid] = g_LUTR[tid];
    __syncthreads();

    #pragma unroll
    for (int i = 0; i < 4; i++) {
        int cl = ty + i * 8;
        int hw = p0 + tx;
        if (hw < HW) {
            int c = c0 + cl;
            size_t idx = ((size_t)n * CIN + c) * HW + hw;
            int v = decode_in(x[idx]);
            tile[cl][tx] = sLA[v];
            g_RX8[idx]   = sLR[v];
        }
    }
    __syncthreads();
    #pragma unroll
    for (int i = 0; i < 4; i++) {
        int pl = ty + i * 8;
        int hw = p0 + pl;
        if (hw < HW) {
            int c = c0 + tx;
            g_A1[((size_t)n * HW + hw) * CIN + c] = tile[tx][pl];
        }
    }
}

// ==================== main GEMMs: ldmatrix + 64-row tiles ====================

// ---- gemm1: 64 pixels x 128 co, K=512, 8 stages of 64 ----
__global__ __launch_bounds__(256, 3) void gemm1_ld() {
    __shared__ int8_t sA[2][64][80];
    __shared__ int8_t sB[2][128][80];
    __shared__ int s_tile;
    int tid  = threadIdx.x;
    int warp = tid >> 5, lane = tid & 31;
    int wm = warp & 1, wn = warp >> 1;          // 2 x 4 warp grid, warp tile 32x32
    int g  = lane >> 2, tig = lane & 3;
    int q  = lane >> 3, rl = lane & 7;
    int lrow = tid >> 2, lcb = (tid & 3) * 16;

    for (;;) {
        if (tid == 0) s_tile = (int)atomicAdd(&g_tick[0], 1u);
        __syncthreads();
        int tile = s_tile;
        if (tile >= G1T) return;
        int p0 = tile * 64;

        int acc[2][4][4];
        #pragma unroll
        for (int mi = 0; mi < 2; mi++)
            #pragma unroll
            for (int ni = 0; ni < 4; ni++)
                #pragma unroll
                for (int e = 0; e < 4; e++) acc[mi][ni][e] = 0;

        auto load_stage = [&](int st, int k0) {
            cp16(smem_u32(&sA[st][lrow][lcb]),
                 &g_A1[(size_t)(p0 + lrow) * CIN + k0 + lcb]);
            #pragma unroll
            for (int it = 0; it < 2; it++) {
                int r = lrow + it * 64;
                cp16(smem_u32(&sB[st][r][lcb]),
                     &g_W1[(size_t)r * CIN + k0 + lcb]);
            }
            cp_commit();
        };

        load_stage(0, 0);
        for (int ks = 0; ks < 8; ks++) {
            int cur = ks & 1;
            if (ks < 7) { load_stage(cur ^ 1, (ks + 1) * 64); cp_wait<1>(); }
            else        { cp_wait<0>(); }
            __syncthreads();
            #pragma unroll
            for (int kk = 0; kk < 64; kk += 32) {
                int a[2][4], b[4][2];
                #pragma unroll
                for (int mi = 0; mi < 2; mi++)
                    ldsm_x4(a[mi], smem_u32(
                        &sA[cur][wm * 32 + mi * 16 + (q & 1) * 8 + rl][(q >> 1) * 16 + kk]));
                #pragma unroll
                for (int p = 0; p < 2; p++) {
                    int bt[4];
                    ldsm_x4(bt, smem_u32(
                        &sB[cur][wn * 32 + p * 16 + (q >> 1) * 8 + rl][(q & 1) * 16 + kk]));
                    b[2 * p][0] = bt[0]; b[2 * p][1] = bt[1];
                    b[2 * p + 1][0] = bt[2]; b[2 * p + 1][1] = bt[3];
                }
                #pragma unroll
                for (int mi = 0; mi < 2; mi++)
                    #pragma unroll
                    for (int ni = 0; ni < 4; ni++)
                        mma_s8(acc[mi][ni], a[mi], b[ni]);
            }
            __syncthreads();
        }

        #pragma unroll
        for (int mi = 0; mi < 2; mi++) {
            int pr = p0 + wm * 32 + mi * 16 + g;
            #pragma unroll
            for (int ni = 0; ni < 4; ni++) {
                int col0 = wn * 32 + ni * 8 + 2 * tig;
                #pragma unroll
                for (int e = 0; e < 4; e++) {
                    int row = pr + ((e >> 1) << 3);
                    int col = col0 + (e & 1);
                    g_O1[(size_t)row * WIDTH + col] = epi1(acc[mi][ni][e], col);
                }
            }
        }
        __syncthreads();
    }
}

// ---- gemm2: implicit 3x3, 64-pixel tiles, 18 stages of (tap, k-half) ----
__global__ __launch_bounds__(256, 3) void gemm2_ld() {
    __shared__ int8_t sA[2][64][80];
    __shared__ int8_t sB[2][128][80];
    __shared__ int s_tile;
    int tid  = threadIdx.x;
    int warp = tid >> 5, lane = tid & 31;
    int wm = warp & 1, wn = warp >> 1;
    int g  = lane >> 2, tig = lane & 3;
    int q  = lane >> 3, rl = lane & 7;
    int arow = tid >> 2, acb = (tid & 3) * 16;  // A loader: 64 rows x 4 chunks
    int brow = tid >> 1, bcb = (tid & 1) * 32;  // B loader: 128 rows x 2x16B

    for (;;) {
        if (tid == 0) s_tile = (int)atomicAdd(&g_tick[1], 1u);
        __syncthreads();
        int tile = s_tile;
        if (tile >= G2T) return;
        int p0 = tile * 64;

        int p  = p0 + arow;
        int n  = p / HW;
        int hw = p % HW;
        int h  = hw / WDIM, w = hw % WDIM;

        int acc[2][4][4];
        #pragma unroll
        for (int mi = 0; mi < 2; mi++)
            #pragma unroll
            for (int ni = 0; ni < 4; ni++)
                #pragma unroll
                for (int e = 0; e < 4; e++) acc[mi][ni][e] = 0;

        auto load_stage = [&](int st, int s) {
            int tap = s >> 1, kh = s & 1;
            int dy = tap / 3 - 1, dx = tap % 3 - 1;
            int hh = h + dy, ww = w + dx;
            bool valid = ((unsigned)hh < HDIM) && ((unsigned)ww < WDIM);
            long long off = valid
                ? ((long long)n * HW + (long long)hh * WDIM + ww) * WIDTH + kh * 64 + acb
                : 0;
            int sz = valid ? 16 : 0;
            cp16p(smem_u32(&sA[st][arow][acb]), &g_O1[off], sz);
            const int8_t* wsrc =
                &g_W2[(size_t)tap * WIDTH * WIDTH + (size_t)brow * WIDTH + kh * 64 + bcb];
            cp16(smem_u32(&sB[st][brow][bcb]),      wsrc);
            cp16(smem_u32(&sB[st][brow][bcb + 16]), wsrc + 16);
            cp_commit();
        };

        load_stage(0, 0);
        for (int s = 0; s < 18; s++) {
            int cur = s & 1;
            if (s < 17) { load_stage(cur ^ 1, s + 1); cp_wait<1>(); }
            else        { cp_wait<0>(); }
            __syncthreads();
            #pragma unroll
            for (int kk = 0; kk < 64; kk += 32) {
                int a[2][4], b[4][2];
                #pragma unroll
                for (int mi = 0; mi < 2; mi++)
                    ldsm_x4(a[mi], smem_u32(
                        &sA[cur][wm * 32 + mi * 16 + (q & 1) * 8 + rl][(q >> 1) * 16 + kk]));
                #pragma unroll
                for (int pp = 0; pp < 2; pp++) {
                    int bt[4];
                    ldsm_x4(bt, smem_u32(
                        &sB[cur][wn * 32 + pp * 16 + (q >> 1) * 8 + rl][(q & 1) * 16 + kk]));
                    b[2 * pp][0] = bt[0]; b[2 * pp][1] = bt[1];
                    b[2 * pp + 1][0] = bt[2]; b[2 * pp + 1][1] = bt[3];
                }
                #pragma unroll
                for (int mi = 0; mi < 2; mi++)
                    #pragma unroll
                    for (int ni = 0; ni < 4; ni++)
                        mma_s8(acc[mi][ni], a[mi], b[ni]);
            }
            __syncthreads();
        }

        #pragma unroll
        for (int mi = 0; mi < 2; mi++) {
            int pr = p0 + wm * 32 + mi * 16 + g;
            #pragma unroll
            for (int ni = 0; ni < 4; ni++) {
                int col0 = wn * 32 + ni * 8 + 2 * tig;
                #pragma unroll
                for (int e = 0; e < 4; e++) {
                    int row = pr + ((e >> 1) << 3);
                    int col = col0 + (e & 1);
                    g_O2[(size_t)row * WIDTH + col] = epi2(acc[mi][ni][e], col);
                }
            }
        }
        __syncthreads();
    }
}

// ---- gemm3: 128x128 tile, K=128 single stage, ldmatrix + residual add ----
__global__ __launch_bounds__(256, 2) void gemm3_ld(float* __restrict__ out) {
    __shared__ int8_t sA[128][144];
    __shared__ int8_t sB[128][144];
    __shared__ int s_tile;
    __shared__ int8_t sLR[256];
    int tid  = threadIdx.x;
    int warp = tid >> 5, lane = tid & 31;
    int wm = warp & 1, wn = warp >> 1;
    int g  = lane >> 2, tig = lane & 3;
    int q  = lane >> 3, rl = lane & 7;
    int lrow = tid >> 1, lcb = (tid & 1) * 64;
    if (tid < 256) sLR[tid] = g_LUTR[tid];

    for (;;) {
        if (tid == 0) s_tile = (int)atomicAdd(&g_tick[2], 1u);
        __syncthreads();
        int tile = s_tile;
        if (tile >= G3T) return;
        int p0  = (tile >> 2) * 128;
        int c00 = (tile & 3) * 128;

        int acc[4][4][4];
        #pragma unroll
        for (int mi = 0; mi < 4; mi++)
            #pragma unroll
            for (int ni = 0; ni < 4; ni++)
                #pragma unroll
                for (int e = 0; e < 4; e++) acc[mi][ni][e] = 0;

        #pragma unroll
        for (int i = 0; i < 4; i++) {
            cp16(smem_u32(&sA[lrow][lcb + i * 16]),
                 &g_O2[(size_t)(p0 + lrow) * WIDTH + lcb + i * 16]);
            cp16(smem_u32(&sB[lrow][lcb + i * 16]),
                 &g_W3[(size_t)(c00 + lrow) * WIDTH + lcb + i * 16]);
        }
        cp_commit();
        cp_wait<0>();
        __syncthreads();

        #pragma unroll
        for (int kk = 0; kk < 128; kk += 32) {
            int a[4][4], b[4][2];
            #pragma unroll
            for (int mi = 0; mi < 4; mi++)
                ldsm_x4(a[mi], smem_u32(
                    &sA[wm * 64 + mi * 16 + (q & 1) * 8 + rl][(q >> 1) * 16 + kk]));
            #pragma unroll
            for (int pp = 0; pp < 2; pp++) {
                int bt[4];
                ldsm_x4(bt, smem_u32(
                    &sB[wn * 32 + pp * 16 + (q >> 1) * 8 + rl][(q & 1) * 16 + kk]));
                b[2 * pp][0] = bt[0]; b[2 * pp][1] = bt[1];
                b[2 * pp + 1][0] = bt[2]; b[2 * pp + 1][1] = bt[3];
            }
            #pragma unroll
            for (int mi = 0; mi < 4; mi++)
                #pragma unroll
                for (int ni = 0; ni < 4; ni++)
                    mma_s8(acc[mi][ni], a[mi], b[ni]);
        }

        #pragma unroll
        for (int mi = 0; mi < 4; mi++) {
            int pr = p0 + wm * 64 + mi * 16 + g;
            #pragma unroll
            for (int ni = 0; ni < 4; ni++) {
                int col0 = c00 + wn * 32 + ni * 8 + 2 * tig;
                #pragma unroll
                for (int e = 0; e < 4; e++) {
                    int row = pr + ((e >> 1) << 3);
                    int co  = col0 + (e & 1);
                    long long qv = rsh(mulM((long long)acc[mi][ni][e] + g_B3[co],
                                            M0_C3), SH_C3) + 128;
                    int v3 = clampi((int)qv, 0, 255);
                    int n  = row / HW;
                    int hw = row % HW;
                    size_t idx = ((size_t)n * COUT + co) * HW + hw;
                    int rv = (int)g_RX8[idx] + (int)sLR[v3] + 128;
                    out[idx] = (float)clampi(rv, 0, 255);
                }
            }
        }
        __syncthreads();
    }
}

// ==================== dp4a reference + checks ====================
__device__ __forceinline__ int dp_conv1(int p, int co) {
    const int* a = (const int*)g_A1 + (size_t)p * (CIN / 4);
    const int* w = (const int*)g_W1 + (size_t)co * (CIN / 4);
    int acc = 0;
    #pragma unroll 8
    for (int j = 0; j < CIN / 4; j++) acc = __dp4a(a[j], w[j], acc);
    return acc;
}
__device__ __forceinline__ int dp_conv2(int p, int co) {
    int n = p / HW, hw = p % HW;
    int h = hw / WDIM, w = hw % WDIM;
    int acc = 0;
    for (int tap = 0; tap < 9; tap++) {
        int hh = h + tap / 3 - 1, ww = w + tap % 3 - 1;
        if ((unsigned)hh >= HDIM || (unsigned)ww >= WDIM) continue;
        const int* a  = (const int*)g_O1 + (size_t)(n * HW + hh * WDIM + ww) * (WIDTH / 4);
        const int* wt = (const int*)g_W2 + ((size_t)tap * WIDTH * WIDTH + (size_t)co * WIDTH) / 4;
        #pragma unroll 8
        for (int j = 0; j < WIDTH / 4; j++) acc = __dp4a(a[j], wt[j], acc);
    }
    return acc;
}
__device__ __forceinline__ int dp_conv3(int p, int co) {
    const int* a = (const int*)g_O2 + (size_t)p * (WIDTH / 4);
    const int* w = (const int*)g_W3 + (size_t)co * (WIDTH / 4);
    int acc = 0;
    #pragma unroll 8
    for (int j = 0; j < WIDTH / 4; j++) acc = __dp4a(a[j], w[j], acc);
    return acc;
}

__global__ __launch_bounds__(256) void check1_kernel() {
    unsigned k = blockIdx.x * 256u + threadIdx.x;
    for (int s = 0; s < 2; s++) {
        unsigned kk = k * 2u + s;
        int p  = (int)((kk * 2654435761u) % PTOT);
        int co = (int)((kk * 40503u) % WIDTH);
        if (epi1(dp_conv1(p, co), co) != g_O1[(size_t)p * WIDTH + co]) g_flag[0] = 1;
    }
}
__global__ __launch_bounds__(256) void check2_kernel() {
    unsigned k = blockIdx.x * 256u + threadIdx.x;
    int p  = (int)((k * 2654435761u) % PTOT);
    int co = (int)((k * 40503u) % WIDTH);
    if (epi2(dp_conv2(p, co), co) != g_O2[(size_t)p * WIDTH + co]) g_flag[1] = 1;
}
__global__ __launch_bounds__(256) void check3_kernel(const unsigned* __restrict__ x,
                                                    const float* __restrict__ out) {
    unsigned k = blockIdx.x * 256u + threadIdx.x;
    for (int s = 0; s < 2; s++) {
        unsigned kk = k * 2u + s;
        int p  = (int)((kk * 2654435761u) % PTOT);
        int co = (int)((kk * 48271u) % COUT);
        int n = p / HW, hw = p % HW;
        size_t idx = ((size_t)n * COUT + co) * HW + hw;
        float want = (float)epi3_add(dp_conv3(p, co), co, decode_in(x[idx]));
        if (want != out[idx]) g_flag[2] = 1;
    }
}

// ==================== fallback GEMMs (proven R10 kernels) ====================
__global__ __launch_bounds__(256, 2) void fb_gemm1() {
    if (g_flag[0] == 0) return;
    __shared__ int8_t sA[2][128][80];
    __shared__ int8_t sB[2][128][80];
    __shared__ int s_tile;
    int tid  = threadIdx.x;
    int warp = tid >> 5, lane = tid & 31;
    int wm = warp & 1, wn = warp >> 1;
    int g  = lane >> 2, tig = lane & 3;
    int lrow  = tid >> 2;
    int lcolb = (tid & 3) * 16;

    for (;;) {
        if (tid == 0) s_tile = (int)atomicAdd(&g_tick[4], 1u);
        __syncthreads();
        int tile = s_tile;
        if (tile >= FB_NT1) return;
        int p0 = tile * 128;

        int acc[4][4][4];
        #pragma unroll
        for (int mi = 0; mi < 4; mi++)
            #pragma unroll
            for (int ni = 0; ni < 4; ni++)
                #pragma unroll
                for (int e = 0; e < 4; e++) acc[mi][ni][e] = 0;

        auto load_stage = [&](int st, int k0) {
            #pragma unroll
            for (int it = 0; it < 2; it++) {
                int r = lrow + it * 64;
                cp16(smem_u32(&sA[st][r][lcolb]),
                     &g_A1[(size_t)(p0 + r) * CIN + k0 + lcolb]);
                cp16(smem_u32(&sB[st][r][lcolb]),
                     &g_W1[(size_t)r * CIN + k0 + lcolb]);
            }
            cp_commit();
        };

        load_stage(0, 0);
        for (int ks = 0; ks < 8; ks++) {
            int cur = ks & 1;
            if (ks < 7) { load_stage(cur ^ 1, (ks + 1) * 64); cp_wait<1>(); }
            else        { cp_wait<0>(); }
            __syncthreads();
            #pragma unroll
            for (int kk = 0; kk < 64; kk += 32) {
                int a[4][4], b[4][2];
                #pragma unroll
                for (int mi = 0; mi < 4; mi++) {
                    int r = wm * 64 + mi * 16;
                    a[mi][0] = *(int*)&sA[cur][r + g][kk + 4 * tig];
                    a[mi][1] = *(int*)&sA[cur][r + g + 8][kk + 4 * tig];
                    a[mi][2] = *(int*)&sA[cur][r + g][kk + 16 + 4 * tig];
                    a[mi][3] = *(int*)&sA[cur][r + g + 8][kk + 16 + 4 * tig];
                }
                #pragma unroll
                for (int ni = 0; ni < 4; ni++) {
                    int cb = wn * 32 + ni * 8;
                    b[ni][0] = *(int*)&sB[cur][cb + g][kk + 4 * tig];
                    b[ni][1] = *(int*)&sB[cur][cb + g][kk + 16 + 4 * tig];
                }
                #pragma unroll
                for (int mi = 0; mi < 4; mi++)
                    #pragma unroll
                    for (int ni = 0; ni < 4; ni++)
                        mma_s8(acc[mi][ni], a[mi], b[ni]);
            }
            __syncthreads();
        }

        #pragma unroll
        for (int mi = 0; mi < 4; mi++) {
            int pr = p0 + wm * 64 + mi * 16 + g;
            #pragma unroll
            for (int ni = 0; ni < 4; ni++) {
                int col0 = wn * 32 + ni * 8 + 2 * tig;
                #pragma unroll
                for (int e = 0; e < 4; e++) {
                    int row = pr + ((e >> 1) << 3);
                    int col = col0 + (e & 1);
                    g_O1[(size_t)row * WIDTH + col] = epi1(acc[mi][ni][e], col);
                }
            }
        }
        __syncthreads();
    }
}

__global__ __launch_bounds__(256, 2) void fb_gemm2() {
    if (g_flag[1] == 0) return;
    __shared__ int8_t sA[2][128][80];
    __shared__ int8_t sB[2][128][80];
    __shared__ int s_tile;
    int tid  = threadIdx.x;
    int warp = tid >> 5, lane = tid & 31;
    int wm = warp & 1, wn = warp >> 1;
    int g  = lane >> 2, tig = lane & 3;
    int lrow  = tid >> 1;
    int lcolb = (tid & 1) * 32;

    for (;;) {
        if (tid == 0) s_tile = (int)atomicAdd(&g_tick[5], 1u);
        __syncthreads();
        int tile = s_tile;
        if (tile >= FB_NT2) return;
        int p0 = tile * 128;
        int p  = p0 + lrow;
        int n  = p / HW;
        int hw = p % HW;
        int h  = hw / WDIM, w = hw % WDIM;

        int acc[4][4][4];
        #pragma unroll
        for (int mi = 0; mi < 4; mi++)
            #pragma unroll
            for (int ni = 0; ni < 4; ni++)
                #pragma unroll
                for (int e = 0; e < 4; e++) acc[mi][ni][e] = 0;

        auto load_stage = [&](int st, int s) {
            int tap = s >> 1, kh = s & 1;
            int dy = tap / 3 - 1, dx = tap % 3 - 1;
            int hh = h + dy, ww = w + dx;
            bool valid = ((unsigned)hh < HDIM) && ((unsigned)ww < WDIM);
            long long off = valid
                ? ((long long)n * HW + (long long)hh * WDIM + ww) * WIDTH + kh * 64 + lcolb
                : 0;
            int sz = valid ? 16 : 0;
            cp16p(smem_u32(&sA[st][lrow][lcolb]),      &g_O1[off],      sz);
            cp16p(smem_u32(&sA[st][lrow][lcolb + 16]), &g_O1[off + 16], sz);
            const int8_t* wsrc =
                &g_W2[(size_t)tap * WIDTH * WIDTH + (size_t)lrow * WIDTH + kh * 64 + lcolb];
            cp16(smem_u32(&sB[st][lrow][lcolb]),      wsrc);
            cp16(smem_u32(&sB[st][lrow][lcolb + 16]), wsrc + 16);
            cp_commit();
        };

        load_stage(0, 0);
        for (int s = 0; s < 18; s++) {
            int cur = s & 1;
            if (s < 17) { load_stage(cur ^ 1, s + 1); cp_wait<1>(); }
            else        { cp_wait<0>(); }
            __syncthreads();
            #pragma unroll
            for (int kk = 0; kk < 64; kk += 32) {
                int a[4][4], b[4][2];
                #pragma unroll
                for (int mi = 0; mi < 4; mi++) {
                    int r = wm * 64 + mi * 16;
                    a[mi][0] = *(int*)&sA[cur][r + g][kk + 4 * tig];
                    a[mi][1] = *(int*)&sA[cur][r + g + 8][kk + 4 * tig];
                    a[mi][2] = *(int*)&sA[cur][r + g][kk + 16 + 4 * tig];
                    a[mi][3] = *(int*)&sA[cur][r + g + 8][kk + 16 + 4 * tig];
                }
                #pragma unroll
                for (int ni = 0; ni < 4; ni++) {
                    int cb = wn * 32 + ni * 8;
                    b[ni][0] = *(int*)&sB[cur][cb + g][kk + 4 * tig];
                    b[ni][1] = *(int*)&sB[cur][cb + g][kk + 16 + 4 * tig];
                }
                #pragma unroll
                for (int mi = 0; mi < 4; mi++)
                    #pragma unroll
                    for (int ni = 0; ni < 4; ni++)
                        mma_s8(acc[mi][ni], a[mi], b[ni]);
            }
            __syncthreads();
        }

        #pragma unroll
        for (int mi = 0; mi < 4; mi++) {
            int pr = p0 + wm * 64 + mi * 16 + g;
            #pragma unroll
            for (int ni = 0; ni < 4; ni++) {
                int col0 = wn * 32 + ni * 8 + 2 * tig;
                #pragma unroll
                for (int e = 0; e < 4; e++) {
                    int row = pr + ((e >> 1) << 3);
                    int col = col0 + (e & 1);
                    g_O2[(size_t)row * WIDTH + col] = epi2(acc[mi][ni][e], col);
                }
            }
        }
        __syncthreads();
    }
}

__global__ __launch_bounds__(256, 2) void fb_gemm3(float* __restrict__ out) {
    if (g_flag[2] == 0) return;
    __shared__ int8_t sA[128][144];
    __shared__ int8_t sB[128][144];
    __shared__ int s_tile;
    int tid  = threadIdx.x;
    int warp = tid >> 5, lane = tid & 31;
    int wm = warp & 1, wn = warp >> 1;
    int g  = lane >> 2, tig = lane & 3;
    int lrow  = tid >> 1;
    int lcolb = (tid & 1) * 64;

    for (;;) {
        if (tid == 0) s_tile = (int)atomicAdd(&g_tick[6], 1u);
        __syncthreads();
        int tile = s_tile;
        if (tile >= FB_NT3) return;
        int p0  = (tile >> 2) * 128;
        int c00 = (tile & 3) * 128;

        int acc[4][4][4];
        #pragma unroll
        for (int mi = 0; mi < 4; mi++)
            #pragma unroll
            for (int ni = 0; ni < 4; ni++)
                #pragma unroll
                for (int e = 0; e < 4; e++) acc[mi][ni][e] = 0;

        #pragma unroll
        for (int i = 0; i < 4; i++) {
            cp16(smem_u32(&sA[lrow][lcolb + i * 16]),
                 &g_O2[(size_t)(p0 + lrow) * WIDTH + lcolb + i * 16]);
            cp16(smem_u32(&sB[lrow][lcolb + i * 16]),
                 &g_W3[(size_t)(c00 + lrow) * WIDTH + lcolb + i * 16]);
        }
        cp_commit();
        cp_wait<0>();
        __syncthreads();

        #pragma unroll
        for (int kk = 0; kk < 128; kk += 32) {
            int a[4][4], b[4][2];
            #pragma unroll
            for (int mi = 0; mi < 4; mi++) {
                int r = wm * 64 + mi * 16;
                a[mi][0] = *(int*)&sA[r + g][kk + 4 * tig];
                a[mi][1] = *(int*)&sA[r + g + 8][kk + 4 * tig];
                a[mi][2] = *(int*)&sA[r + g][kk + 16 + 4 * tig];
                a[mi][3] = *(int*)&sA[r + g + 8][kk + 16 + 4 * tig];
            }
            #pragma unroll
            for (int ni = 0; ni < 4; ni++) {
                int cb = wn * 32 + ni * 8;
                b[ni][0] = *(int*)&sB[cb + g][kk + 4 * tig];
                b[ni][1] = *(int*)&sB[cb + g][kk + 16 + 4 * tig];
            }
            #pragma unroll
            for (int mi = 0; mi < 4; mi++)
                #pragma unroll
                for (int ni = 0; ni < 4; ni++)
                    mma_s8(acc[mi][ni], a[mi], b[ni]);
        }

        #pragma unroll
        for (int mi = 0; mi < 4; mi++) {
            int pr = p0 + wm * 64 + mi * 16 + g;
            #pragma unroll
            for (int ni = 0; ni < 4; ni++) {
                int col0 = c00 + wn * 32 + ni * 8 + 2 * tig;
                #pragma unroll
                for (int e = 0; e < 4; e++) {
                    int row = pr + ((e >> 1) << 3);
                    int co  = col0 + (e & 1);
                    long long q = rsh(mulM((long long)acc[mi][ni][e] + g_B3[co],
                                           M0_C3), SH_C3) + 128;
                    int v3 = clampi((int)q, 0, 255);
                    int n  = row / HW;
                    int hw = row % HW;
                    size_t idx = ((size_t)n * COUT + co) * HW + hw;
                    int r = (int)g_RX8[idx] + (int)g_LUTR[v3] + 128;
                    out[idx] = (float)clampi(r, 0, 255);
                }
            }
        }
        __syncthreads();
    }
}

// ---------------- launch ----------------
extern "C" void kernel_launch(void* const* d_in, const int* in_sizes, int n_in,
                              void* d_out, int out_size) {
    int ix = -1, iw1 = -1, ib1 = -1, iw2 = -1, ib2 = -1, iw3 = -1, ib3 = -1;
    for (int i = 0; i < n_in; i++) {
        long long s = in_sizes[i];
        if      (s == (long long)PTOT * CIN)        { ix = i; }
        else if (s == (long long)9 * WIDTH * WIDTH) { iw2 = i; }
        else if (s == COUT)                         { ib3 = i; }
        else if (s == (long long)WIDTH * CIN)       { if (iw1 < 0) iw1 = i; else iw3 = i; }
        else if (s == WIDTH)                        { if (ib1 < 0) ib1 = i; else ib2 = i; }
    }
    if (ix < 0)  ix = 0;
    if (iw1 < 0) iw1 = 1;
    if (ib1 < 0) ib1 = 2;
    if (iw2 < 0) iw2 = 3;
    if (ib2 < 0) ib2 = 4;
    if (iw3 < 0) iw3 = 5;
    if (ib3 < 0) ib3 = 6;

    const unsigned* x  = (const unsigned*)d_in[ix];
    const unsigned* w1 = (const unsigned*)d_in[iw1];
    const unsigned* b1 = (const unsigned*)d_in[ib1];
    const unsigned* w2 = (const unsigned*)d_in[iw2];
    const unsigned* b2 = (const unsigned*)d_in[ib2];
    const unsigned* w3 = (const unsigned*)d_in[iw3];
    const unsigned* b3 = (const unsigned*)d_in[ib3];
    float* out = (float*)d_out;

    prep_weights<<<576, 256>>>(w1, b1, w2, b2, w3, b3);
    rescale_kernel<<<dim3(25, 16, 64), dim3(32, 8)>>>(x);

    gemm1_ld<<<G12GRID, 256>>>();
    check1_kernel<<<FBGRID, 256>>>();
    fb_gemm1<<<FBGRID, 256>>>();

    gemm2_ld<<<G12GRID, 256>>>();
    check2_kernel<<<FBGRID, 256>>>();
    fb_gemm2<<<FBGRID, 256>>>();

    gemm3_ld<<<G3GRID, 256>>>(out);
    check3_kernel<<<FBGRID, 256>>>(x, out);
    fb_gemm3<<<FBGRID, 256>>>(out);
}

// round 15
// speedup vs baseline: 2.4185x; 2.4185x over previous
#include <cuda_runtime.h>
#include <cstdint>

// ---------------- problem constants ----------------
#define NB    64
#define CIN   512
#define HDIM  28
#define WDIM  28
#define HW    784
#define PTOT  (NB*HW)       // 50176
#define WIDTH 128
#define COUT  512

#define G1T   784           // 64-pixel tiles
#define G2T   784
#define G3T   1568          // 128-pixel x 128-chan tiles
#define G12GRID 444         // 148 x 3
#define G3GRID  296

// quantization constants
#define M0_RS 1073741824LL
#define SH_RS 4
#define M0_C1 1288490189LL
#define SH_C1 12
#define M0_C2 1288490189LL
#define SH_C2 10
#define M0_C3 1288490189LL
#define SH_C3 10
#define M0_B  1073741824LL
#define SH_B  1

// ---------------- scratch ----------------
__device__ int8_t g_A1[(size_t)PTOT * CIN];
__device__ int8_t g_O1[(size_t)PTOT * WIDTH];
__device__ int8_t g_O2[(size_t)PTOT * WIDTH];
__device__ int8_t g_RX8[(size_t)PTOT * COUT];
__device__ int8_t g_W1[WIDTH * CIN];
__device__ int8_t g_W2[9 * WIDTH * WIDTH];
__device__ int8_t g_W3[COUT * WIDTH];
__device__ int    g_B1[WIDTH];
__device__ int    g_B2[WIDTH];
__device__ int    g_B3[COUT];
__device__ int8_t g_LUTA[256];
__device__ int8_t g_LUTR[256];
__device__ unsigned g_tick[4];

// ---------------- helpers ----------------
__device__ __forceinline__ unsigned smem_u32(const void* p) {
    return (unsigned)__cvta_generic_to_shared(p);
}
__device__ __forceinline__ void cp16(unsigned dst, const void* src) {
    asm volatile("cp.async.ca.shared.global [%0], [%1], 16;\n" :: "r"(dst), "l"(src));
}
__device__ __forceinline__ void cp16p(unsigned dst, const void* src, int src_sz) {
    asm volatile("cp.async.ca.shared.global [%0], [%1], 16, %2;\n"
                 :: "r"(dst), "l"(src), "r"(src_sz));
}
__device__ __forceinline__ void cp_commit() { asm volatile("cp.async.commit_group;\n"); }
template <int N>
__device__ __forceinline__ void cp_wait() { asm volatile("cp.async.wait_group %0;\n" :: "n"(N)); }

__device__ __forceinline__ void ldsm_x4(int* r, unsigned addr) {
    asm volatile("ldmatrix.sync.aligned.m8n8.x4.shared.b16 {%0,%1,%2,%3}, [%4];"
                 : "=r"(r[0]), "=r"(r[1]), "=r"(r[2]), "=r"(r[3]) : "r"(addr));
}

__device__ __forceinline__ int decode_in(unsigned u) {
    float f = __uint_as_float(u);
    float af = fabsf(f);
    if (af >= 1e-30f && af <= 1e7f) return __float2int_rn(f);
    return (int)u;
}
__device__ __forceinline__ long long mulM(long long x, long long m0) {
    long long prod = x * m0;
    long long nudge = (prod >= 0) ? (1LL << 30) : (1LL - (1LL << 30));
    return (prod + nudge) >> 31;
}
__device__ __forceinline__ long long rsh(long long x, int s) {
    long long mask = (1LL << s) - 1;
    long long rem = x & mask;
    long long thr = (mask >> 1) + (long long)(x < 0);
    return (x >> s) + (long long)(rem > thr);
}
__device__ __forceinline__ int clampi(int v, int lo, int hi) {
    return v < lo ? lo : (v > hi ? hi : v);
}
__device__ __forceinline__ int8_t epi1(int acc, int co) {
    long long q = rsh(mulM((long long)acc + g_B1[co], M0_C1), SH_C1) + 128;
    return (int8_t)(clampi((int)q, 0, 255) - 128);
}
__device__ __forceinline__ int8_t epi2(int acc, int co) {
    long long q = rsh(mulM((long long)acc + g_B2[co], M0_C2), SH_C2) + 128;
    return (int8_t)(clampi((int)q, 0, 255) - 128);
}

__device__ __forceinline__ void mma_s8(int* c, const int* a, const int* b) {
    asm volatile(
        "mma.sync.aligned.m16n8k32.row.col.s32.s8.s8.s32 "
        "{%0,%1,%2,%3},{%4,%5,%6,%7},{%8,%9},{%0,%1,%2,%3};\n"
        : "+r"(c[0]), "+r"(c[1]), "+r"(c[2]), "+r"(c[3])
        : "r"(a[0]), "r"(a[1]), "r"(a[2]), "r"(a[3]), "r"(b[0]), "r"(b[1]));
}

// ---------------- weight prep ----------------
__global__ __launch_bounds__(256) void prep_weights(
        const unsigned* __restrict__ w1, const unsigned* __restrict__ b1,
        const unsigned* __restrict__ w2, const unsigned* __restrict__ b2,
        const unsigned* __restrict__ w3, const unsigned* __restrict__ b3) {
    int t = blockIdx.x * blockDim.x + threadIdx.x;
    if (t < 4) g_tick[t] = 0u;
    if (t < 256) {
        long long d = (long long)t - 128;
        long long q = rsh(mulM(d, M0_RS), SH_RS) + 8;
        g_LUTA[t] = (int8_t)(clampi((int)q, 0, 15) - 8);
        g_LUTR[t] = (int8_t)rsh(mulM(d, M0_B), SH_B);
    }
    if (t < WIDTH * CIN)  g_W1[t] = (int8_t)decode_in(w1[t]);
    if (t < COUT * WIDTH) g_W3[t] = (int8_t)decode_in(w3[t]);
    if (t < WIDTH * WIDTH * 9) {
        int co = t / (WIDTH * 9);
        int r  = t % (WIDTH * 9);
        int ci = r / 9;
        int k  = r % 9;
        g_W2[(size_t)k * WIDTH * WIDTH + (size_t)co * WIDTH + ci] =
            (int8_t)decode_in(w2[t]);
    }
    if (t < WIDTH) { g_B1[t] = decode_in(b1[t]); g_B2[t] = decode_in(b2[t]); }
    if (t < COUT)  { g_B3[t] = decode_in(b3[t]); }
}

// ---------------- rescale + transpose + residual ----------------
__global__ __launch_bounds__(256) void rescale_kernel(const unsigned* __restrict__ x) {
    __shared__ int8_t tile[32][33];
    __shared__ int8_t sLA[256], sLR[256];
    int n  = blockIdx.z;
    int c0 = blockIdx.y * 32;
    int p0 = blockIdx.x * 32;
    int tx = threadIdx.x, ty = threadIdx.y;
    int tid = ty * 32 + tx;
    sLA[tid] = g_LUTA[tid];
    sLR[tid] = g_LUTR[tid];
    __syncthreads();

    #pragma unroll
    for (int i = 0; i < 4; i++) {
        int cl = ty + i * 8;
        int hw = p0 + tx;
        if (hw < HW) {
            int c = c0 + cl;
            size_t idx = ((size_t)n * CIN + c) * HW + hw;
            int v = decode_in(x[idx]);
            tile[cl][tx] = sLA[v];
            g_RX8[idx]   = sLR[v];
        }
    }
    __syncthreads();
    #pragma unroll
    for (int i = 0; i < 4; i++) {
        int pl = ty + i * 8;
        int hw = p0 + pl;
        if (hw < HW) {
            int c = c0 + tx;
            g_A1[((size_t)n * HW + hw) * CIN + c] = tile[tx][pl];
        }
    }
}

// ---- gemm1: 64 pixels x 128 co, K=512, 8 stages of 64 ----
__global__ __launch_bounds__(256, 3) void gemm1_ld() {
    __shared__ int8_t sA[2][64][80];
    __shared__ int8_t sB[2][128][80];
    __shared__ int s_tile;
    int tid  = threadIdx.x;
    int warp = tid >> 5, lane = tid & 31;
    int wm = warp & 1, wn = warp >> 1;          // 2 x 4 warp grid, warp tile 32x32
    int g  = lane >> 2, tig = lane & 3;
    int q  = lane >> 3, rl = lane & 7;
    int lrow = tid >> 2, lcb = (tid & 3) * 16;

    for (;;) {
        if (tid == 0) s_tile = (int)atomicAdd(&g_tick[0], 1u);
        __syncthreads();
        int tile = s_tile;
        if (tile >= G1T) return;
        int p0 = tile * 64;

        int acc[2][4][4];
        #pragma unroll
        for (int mi = 0; mi < 2; mi++)
            #pragma unroll
            for (int ni = 0; ni < 4; ni++)
                #pragma unroll
                for (int e = 0; e < 4; e++) acc[mi][ni][e] = 0;

        auto load_stage = [&](int st, int k0) {
            cp16(smem_u32(&sA[st][lrow][lcb]),
                 &g_A1[(size_t)(p0 + lrow) * CIN + k0 + lcb]);
            #pragma unroll
            for (int it = 0; it < 2; it++) {
                int r = lrow + it * 64;
                cp16(smem_u32(&sB[st][r][lcb]),
                     &g_W1[(size_t)r * CIN + k0 + lcb]);
            }
            cp_commit();
        };

        load_stage(0, 0);
        for (int ks = 0; ks < 8; ks++) {
            int cur = ks & 1;
            if (ks < 7) { load_stage(cur ^ 1, (ks + 1) * 64); cp_wait<1>(); }
            else        { cp_wait<0>(); }
            __syncthreads();
            #pragma unroll
            for (int kk = 0; kk < 64; kk += 32) {
                int a[2][4], b[4][2];
                #pragma unroll
                for (int mi = 0; mi < 2; mi++)
                    ldsm_x4(a[mi], smem_u32(
                        &sA[cur][wm * 32 + mi * 16 + (q & 1) * 8 + rl][(q >> 1) * 16 + kk]));
                #pragma unroll
                for (int p = 0; p < 2; p++) {
                    int bt[4];
                    ldsm_x4(bt, smem_u32(
                        &sB[cur][wn * 32 + p * 16 + (q >> 1) * 8 + rl][(q & 1) * 16 + kk]));
                    b[2 * p][0] = bt[0]; b[2 * p][1] = bt[1];
                    b[2 * p + 1][0] = bt[2]; b[2 * p + 1][1] = bt[3];
                }
                #pragma unroll
                for (int mi = 0; mi < 2; mi++)
                    #pragma unroll
                    for (int ni = 0; ni < 4; ni++)
                        mma_s8(acc[mi][ni], a[mi], b[ni]);
            }
            __syncthreads();
        }

        #pragma unroll
        for (int mi = 0; mi < 2; mi++) {
            int pr = p0 + wm * 32 + mi * 16 + g;
            #pragma unroll
            for (int ni = 0; ni < 4; ni++) {
                int col0 = wn * 32 + ni * 8 + 2 * tig;
                #pragma unroll
                for (int e = 0; e < 4; e++) {
                    int row = pr + ((e >> 1) << 3);
                    int col = col0 + (e & 1);
                    g_O1[(size_t)row * WIDTH + col] = epi1(acc[mi][ni][e], col);
                }
            }
        }
        __syncthreads();
    }
}

// ---- gemm2: implicit 3x3, 64-pixel tiles, 18 stages of (tap, k-half) ----
__global__ __launch_bounds__(256, 3) void gemm2_ld() {
    __shared__ int8_t sA[2][64][80];
    __shared__ int8_t sB[2][128][80];
    __shared__ int s_tile;
    int tid  = threadIdx.x;
    int warp = tid >> 5, lane = tid & 31;
    int wm = warp & 1, wn = warp >> 1;
    int g  = lane >> 2, tig = lane & 3;
    int q  = lane >> 3, rl = lane & 7;
    int arow = tid >> 2, acb = (tid & 3) * 16;  // A loader: 64 rows x 4 chunks
    int brow = tid >> 1, bcb = (tid & 1) * 32;  // B loader: 128 rows x 2x16B

    for (;;) {
        if (tid == 0) s_tile = (int)atomicAdd(&g_tick[1], 1u);
        __syncthreads();
        int tile = s_tile;
        if (tile >= G2T) return;
        int p0 = tile * 64;

        int p  = p0 + arow;
        int n  = p / HW;
        int hw = p % HW;
        int h  = hw / WDIM, w = hw % WDIM;

        int acc[2][4][4];
        #pragma unroll
        for (int mi = 0; mi < 2; mi++)
            #pragma unroll
            for (int ni = 0; ni < 4; ni++)
                #pragma unroll
                for (int e = 0; e < 4; e++) acc[mi][ni][e] = 0;

        auto load_stage = [&](int st, int s) {
            int tap = s >> 1, kh = s & 1;
            int dy = tap / 3 - 1, dx = tap % 3 - 1;
            int hh = h + dy, ww = w + dx;
            bool valid = ((unsigned)hh < HDIM) && ((unsigned)ww < WDIM);
            long long off = valid
                ? ((long long)n * HW + (long long)hh * WDIM + ww) * WIDTH + kh * 64 + acb
                : 0;
            int sz = valid ? 16 : 0;
            cp16p(smem_u32(&sA[st][arow][acb]), &g_O1[off], sz);
            const int8_t* wsrc =
                &g_W2[(size_t)tap * WIDTH * WIDTH + (size_t)brow * WIDTH + kh * 64 + bcb];
            cp16(smem_u32(&sB[st][brow][bcb]),      wsrc);
            cp16(smem_u32(&sB[st][brow][bcb + 16]), wsrc + 16);
            cp_commit();
        };

        load_stage(0, 0);
        for (int s = 0; s < 18; s++) {
            int cur = s & 1;
            if (s < 17) { load_stage(cur ^ 1, s + 1); cp_wait<1>(); }
            else        { cp_wait<0>(); }
            __syncthreads();
            #pragma unroll
            for (int kk = 0; kk < 64; kk += 32) {
                int a[2][4], b[4][2];
                #pragma unroll
                for (int mi = 0; mi < 2; mi++)
                    ldsm_x4(a[mi], smem_u32(
                        &sA[cur][wm * 32 + mi * 16 + (q & 1) * 8 + rl][(q >> 1) * 16 + kk]));
                #pragma unroll
                for (int pp = 0; pp < 2; pp++) {
                    int bt[4];
                    ldsm_x4(bt, smem_u32(
                        &sB[cur][wn * 32 + pp * 16 + (q >> 1) * 8 + rl][(q & 1) * 16 + kk]));
                    b[2 * pp][0] = bt[0]; b[2 * pp][1] = bt[1];
                    b[2 * pp + 1][0] = bt[2]; b[2 * pp + 1][1] = bt[3];
                }
                #pragma unroll
                for (int mi = 0; mi < 2; mi++)
                    #pragma unroll
                    for (int ni = 0; ni < 4; ni++)
                        mma_s8(acc[mi][ni], a[mi], b[ni]);
            }
            __syncthreads();
        }

        #pragma unroll
        for (int mi = 0; mi < 2; mi++) {
            int pr = p0 + wm * 32 + mi * 16 + g;
            #pragma unroll
            for (int ni = 0; ni < 4; ni++) {
                int col0 = wn * 32 + ni * 8 + 2 * tig;
                #pragma unroll
                for (int e = 0; e < 4; e++) {
                    int row = pr + ((e >> 1) << 3);
                    int col = col0 + (e & 1);
                    g_O2[(size_t)row * WIDTH + col] = epi2(acc[mi][ni][e], col);
                }
            }
        }
        __syncthreads();
    }
}

// ---- gemm3: 128x128 tile, K=128 single stage, ldmatrix + residual add ----
__global__ __launch_bounds__(256, 2) void gemm3_ld(float* __restrict__ out) {
    __shared__ int8_t sA[128][144];
    __shared__ int8_t sB[128][144];
    __shared__ int s_tile;
    __shared__ int8_t sLR[256];
    int tid  = threadIdx.x;
    int warp = tid >> 5, lane = tid & 31;
    int wm = warp & 1, wn = warp >> 1;
    int g  = lane >> 2, tig = lane & 3;
    int q  = lane >> 3, rl = lane & 7;
    int lrow = tid >> 1, lcb = (tid & 1) * 64;
    if (tid < 256) sLR[tid] = g_LUTR[tid];

    for (;;) {
        if (tid == 0) s_tile = (int)atomicAdd(&g_tick[2], 1u);
        __syncthreads();
        int tile = s_tile;
        if (tile >= G3T) return;
        int p0  = (tile >> 2) * 128;
        int c00 = (tile & 3) * 128;

        int acc[4][4][4];
        #pragma unroll
        for (int mi = 0; mi < 4; mi++)
            #pragma unroll
            for (int ni = 0; ni < 4; ni++)
                #pragma unroll
                for (int e = 0; e < 4; e++) acc[mi][ni][e] = 0;

        #pragma unroll
        for (int i = 0; i < 4; i++) {
            cp16(smem_u32(&sA[lrow][lcb + i * 16]),
                 &g_O2[(size_t)(p0 + lrow) * WIDTH + lcb + i * 16]);
            cp16(smem_u32(&sB[lrow][lcb + i * 16]),
                 &g_W3[(size_t)(c00 + lrow) * WIDTH + lcb + i * 16]);
        }
        cp_commit();
        cp_wait<0>();
        __syncthreads();

        #pragma unroll
        for (int kk = 0; kk < 128; kk += 32) {
            int a[4][4], b[4][2];
            #pragma unroll
            for (int mi = 0; mi < 4; mi++)
                ldsm_x4(a[mi], smem_u32(
                    &sA[wm * 64 + mi * 16 + (q & 1) * 8 + rl][(q >> 1) * 16 + kk]));
            #pragma unroll
            for (int pp = 0; pp < 2; pp++) {
                int bt[4];
                ldsm_x4(bt, smem_u32(
                    &sB[wn * 32 + pp * 16 + (q >> 1) * 8 + rl][(q & 1) * 16 + kk]));
                b[2 * pp][0] = bt[0]; b[2 * pp][1] = bt[1];
                b[2 * pp + 1][0] = bt[2]; b[2 * pp + 1][1] = bt[3];
            }
            #pragma unroll
            for (int mi = 0; mi < 4; mi++)
                #pragma unroll
                for (int ni = 0; ni < 4; ni++)
                    mma_s8(acc[mi][ni], a[mi], b[ni]);
        }

        #pragma unroll
        for (int mi = 0; mi < 4; mi++) {
            int pr = p0 + wm * 64 + mi * 16 + g;
            #pragma unroll
            for (int ni = 0; ni < 4; ni++) {
                int col0 = c00 + wn * 32 + ni * 8 + 2 * tig;
                #pragma unroll
                for (int e = 0; e < 4; e++) {
                    int row = pr + ((e >> 1) << 3);
                    int co  = col0 + (e & 1);
                    long long qv = rsh(mulM((long long)acc[mi][ni][e] + g_B3[co],
                                            M0_C3), SH_C3) + 128;
                    int v3 = clampi((int)qv, 0, 255);
                    int n  = row / HW;
                    int hw = row % HW;
                    size_t idx = ((size_t)n * COUT + co) * HW + hw;
                    int rv = (int)g_RX8[idx] + (int)sLR[v3] + 128;
                    out[idx] = (float)clampi(rv, 0, 255);
                }
            }
        }
        __syncthreads();
    }
}

// ---------------- launch ----------------
extern "C" void kernel_launch(void* const* d_in, const int* in_sizes, int n_in,
                              void* d_out, int out_size) {
    int ix = -1, iw1 = -1, ib1 = -1, iw2 = -1, ib2 = -1, iw3 = -1, ib3 = -1;
    for (int i = 0; i < n_in; i++) {
        long long s = in_sizes[i];
        if      (s == (long long)PTOT * CIN)        { ix = i; }
        else if (s == (long long)9 * WIDTH * WIDTH) { iw2 = i; }
        else if (s == COUT)                         { ib3 = i; }
        else if (s == (long long)WIDTH * CIN)       { if (iw1 < 0) iw1 = i; else iw3 = i; }
        else if (s == WIDTH)                        { if (ib1 < 0) ib1 = i; else ib2 = i; }
    }
    if (ix < 0)  ix = 0;
    if (iw1 < 0) iw1 = 1;
    if (ib1 < 0) ib1 = 2;
    if (iw2 < 0) iw2 = 3;
    if (ib2 < 0) ib2 = 4;
    if (iw3 < 0) iw3 = 5;
    if (ib3 < 0) ib3 = 6;

    const unsigned* x  = (const unsigned*)d_in[ix];
    const unsigned* w1 = (const unsigned*)d_in[iw1];
    const unsigned* b1 = (const unsigned*)d_in[ib1];
    const unsigned* w2 = (const unsigned*)d_in[iw2];
    const unsigned* b2 = (const unsigned*)d_in[ib2];
    const unsigned* w3 = (const unsigned*)d_in[iw3];
    const unsigned* b3 = (const unsigned*)d_in[ib3];
    float* out = (float*)d_out;

    prep_weights<<<576, 256>>>(w1, b1, w2, b2, w3, b3);
    rescale_kernel<<<dim3(25, 16, 64), dim3(32, 8)>>>(x);
    gemm1_ld<<<G12GRID, 256>>>();
    gemm2_ld<<<G12GRID, 256>>>();
    gemm3_ld<<<G3GRID, 256>>>(out);
}